// round 10
// baseline (speedup 1.0000x reference)
#include <cuda_runtime.h>
#include <cstdint>

#define HW 65536           // 256*256
#define NB 8
#define NC 32
#define NBC 256

#define MIX_BLOCKS 4096    // 512 px-chunks (128 px each) x 8 batches
#define POOL_BLOCKS 1024   // 256 (b,c) x 4 row-chunks

__device__ __align__(16) float g_feat[NB * NC * HW];
__device__ float g_pp[NBC * 4 * 25];
__device__ float g_filt[NBC * 25];

// ---------------------------------------------------------------------------
// Kernel 1: FUSED channel-mix + adaptive-pool-partials, block-specialized.
// Mix path: warp = 8 out-channels x 64 px (1 float2/lane, 16 scalar accs).
//   Block = 8 warps = 4 och-groups x 2 px-segments covering 128 px x 32 och.
//   Per i-step: 1 LDG.64 (x is L2-resident for 3 of 4 och-groups) +
//   2 LDS.128 (weights, broadcast) + 16 FFMA. ~50 regs -> 5 blocks/SM.
// Pool path: DRAM-streaming partial pooling of x; co-resides with mix
//   blocks and backfills mix's ragged last wave.
// grid = 5120, block = 256
// ---------------------------------------------------------------------------
__global__ __launch_bounds__(256) void mixpool_kernel(
    const float* __restrict__ x,
    const float* __restrict__ w,
    const float* __restrict__ bias)
{
    if (blockIdx.x < MIX_BLOCKS) {
        // ------------------------- mix path -------------------------
        __shared__ float ws[32 * 32];   // [i][o] transposed
        __shared__ float bs[32];

        int tid = threadIdx.x;
        for (int idx = tid; idx < 1024; idx += 256) {
            int i = idx >> 5, o = idx & 31;
            ws[i * 32 + o] = w[o * 32 + i];
        }
        if (tid < 32)
            bs[tid] = bias[tid];
        __syncthreads();

        int wid  = tid >> 5;
        int lane = tid & 31;
        int og = wid & 3;              // och group: og*8 .. og*8+7
        int s  = wid >> 2;             // px segment (32 float2 each)

        int b  = blockIdx.x >> 9;      // batch
        int cx = blockIdx.x & 511;     // 128-px chunk within image
        size_t pixpair = (size_t)cx * 64 + s * 32 + lane;    // float2 idx
        const float2* xp = (const float2*)x
                         + (size_t)b * (NC * (HW / 2)) + pixpair;

        float ax[8], ay[8];
#pragma unroll
        for (int k = 0; k < 8; k++) {
            float bv = bs[og * 8 + k];
            ax[k] = bv;
            ay[k] = bv;
        }

#pragma unroll 8
        for (int i = 0; i < 32; i++) {
            float2 xv = xp[(size_t)i * (HW / 2)];
            const float4* wr = (const float4*)(ws + i * 32 + og * 8);
            float4 w0 = wr[0], w1 = wr[1];
            float wv[8] = {w0.x, w0.y, w0.z, w0.w, w1.x, w1.y, w1.z, w1.w};
#pragma unroll
            for (int k = 0; k < 8; k++) {
                ax[k] = fmaf(wv[k], xv.x, ax[k]);
                ay[k] = fmaf(wv[k], xv.y, ay[k]);
            }
        }

        float2* fb = (float2*)g_feat + (size_t)b * (NC * (HW / 2)) + pixpair;
#pragma unroll
        for (int k = 0; k < 8; k++)
            fb[(size_t)(og * 8 + k) * (HW / 2)] = make_float2(ax[k], ay[k]);

    } else {
        // ------------------------- pool path -------------------------
        // Row bins [0,52)[51,103)[102,154)[153,205)[204,256) (overlap).
        __shared__ float pool[25];
        int idx = blockIdx.x - MIX_BLOCKS;
        int bc = idx >> 2;             // (b*32 + channel)
        int q  = idx & 3;              // 64-row chunk
        int w_ = threadIdx.x;          // column
        if (w_ < 25) pool[w_] = 0.0f;
        __syncthreads();

        const float* img = x + (size_t)bc * HW + (size_t)q * 64 * 256;

        float cs[5] = {0.f, 0.f, 0.f, 0.f, 0.f};
#pragma unroll
        for (int r = 0; r < 64; r++) {
            int h = q * 64 + r;
            float v = img[r * 256 + w_];
            if (h < 52)              cs[0] += v;
            if (h >= 51 && h < 103)  cs[1] += v;
            if (h >= 102 && h < 154) cs[2] += v;
            if (h >= 153 && h < 205) cs[3] += v;
            if (h >= 204)            cs[4] += v;
        }

#pragma unroll
        for (int l = 0; l < 5; l++) {
            int s0 = (l * 256) / 5;
            int e0 = ((l + 1) * 256 + 4) / 5;
            if (w_ >= s0 && w_ < e0) {
#pragma unroll
                for (int k = 0; k < 5; k++)
                    if (cs[k] != 0.0f)
                        atomicAdd(&pool[k * 5 + l], cs[k]);
            }
        }
        __syncthreads();
        if (w_ < 25)
            g_pp[(bc * 4 + q) * 25 + w_] = pool[w_];
    }
}

// ---------------------------------------------------------------------------
// Kernel 2: filt[b,o,kl] = bias[o] + sum_i w[o,i] * px[b,i,kl]
// (pooling commutes with the 1x1 conv: pool matrix is row-stochastic)
// grid = 8, block = 800
// ---------------------------------------------------------------------------
__global__ void filt_kernel(const float* __restrict__ w,
                            const float* __restrict__ bias)
{
    __shared__ float spx[800];
    int b = blockIdx.x;
    int t = threadIdx.x;
    int i  = t / 25;
    int kl = t - i * 25;

    float s = 0.0f;
#pragma unroll
    for (int q = 0; q < 4; q++)
        s += g_pp[((b * 32 + i) * 4 + q) * 25 + kl];
    spx[t] = s * (1.0f / 2704.0f);
    __syncthreads();

    float acc = bias[i];
#pragma unroll
    for (int ic = 0; ic < 32; ic++)
        acc += w[i * 32 + ic] * spx[ic * 25 + kl];
    g_filt[b * 800 + t] = acc;
}

// ---------------------------------------------------------------------------
// Kernel 3: depthwise 5x5 'same' conv — occupancy-first scalar version
// (measured 38 us, occ 91%, issue 70%). 64x32 tile, 36x68 halo, thread =
// 1 col x 8 rows, division-free halo staging.
// grid = (32, 256), block = 256
// ---------------------------------------------------------------------------
__global__ __launch_bounds__(256) void conv_kernel(float* __restrict__ out)
{
    __shared__ float sh[36 * 68];

    int bc  = blockIdx.y;
    int tile = blockIdx.x;
    int tx0 = (tile & 3) * 64;
    int ty0 = (tile >> 2) * 32;

    const float* img = g_feat + (size_t)bc * HW;

    float f[25];
#pragma unroll
    for (int t = 0; t < 25; t++) f[t] = g_filt[bc * 25 + t];

    {
        int c  = threadIdx.x & 63;
        int r0 = threadIdx.x >> 6;
        int gx = tx0 + c - 2;
        bool cin = (unsigned)gx < 256u;
#pragma unroll
        for (int k = 0; k < 9; k++) {
            int r = r0 + k * 4;
            int gy = ty0 + r - 2;
            float v = 0.0f;
            if (cin && (unsigned)gy < 256u)
                v = img[gy * 256 + gx];
            sh[r * 68 + c] = v;
        }
        int c2 = 64 + (threadIdx.x & 3);
        int r2 = threadIdx.x >> 2;
        if (r2 < 36) {
            int gy = ty0 + r2 - 2;
            int gx2 = tx0 + c2 - 2;
            float v = 0.0f;
            if ((unsigned)gy < 256u && (unsigned)gx2 < 256u)
                v = img[gy * 256 + gx2];
            sh[r2 * 68 + c2] = v;
        }
    }
    __syncthreads();

    int x  = threadIdx.x & 63;
    int ys = (threadIdx.x >> 6) * 8;

    float acc[8];
#pragma unroll
    for (int j = 0; j < 8; j++) acc[j] = 0.0f;

#pragma unroll
    for (int r = 0; r < 12; r++) {
        const float* row = sh + (ys + r) * 68 + x;
        float v0 = row[0];
        float v1 = row[1];
        float v2 = row[2];
        float v3 = row[3];
        float v4 = row[4];
#pragma unroll
        for (int ky = 0; ky < 5; ky++) {
            int j = r - ky;
            if (j >= 0 && j < 8) {
                acc[j] += v0 * f[ky * 5 + 0];
                acc[j] += v1 * f[ky * 5 + 1];
                acc[j] += v2 * f[ky * 5 + 2];
                acc[j] += v3 * f[ky * 5 + 3];
                acc[j] += v4 * f[ky * 5 + 4];
            }
        }
    }

    float* op = out + (size_t)bc * HW + (size_t)(ty0 + ys) * 256 + tx0 + x;
#pragma unroll
    for (int j = 0; j < 8; j++)
        op[j * 256] = acc[j];
}

// ---------------------------------------------------------------------------
extern "C" void kernel_launch(void* const* d_in, const int* in_sizes, int n_in,
                              void* d_out, int out_size)
{
    const float* x    = (const float*)d_in[0];   // [8, 32, 256, 256]
    const float* w    = (const float*)d_in[1];   // [32, 32]
    const float* bias = (const float*)d_in[2];   // [32]
    float* out = (float*)d_out;                  // [8, 32, 256, 256]

    mixpool_kernel<<<MIX_BLOCKS + POOL_BLOCKS, 256>>>(x, w, bias);
    filt_kernel<<<NB, 800>>>(w, bias);
    conv_kernel<<<dim3(32, NBC), 256>>>(out);
}

// round 11
// speedup vs baseline: 1.2310x; 1.2310x over previous
#include <cuda_runtime.h>
#include <cstdint>

#define HW 65536           // 256*256
#define NB 8
#define NC 32
#define NBC 256

#define MIX_BLOCKS 2048    // 256 px-chunks x 8 batches (R9 config)
#define POOL_BLOCKS 1024   // 256 (b,c) x 4 row-chunks
#define MIX_PER_BATCH 256
#define POOL_PER_BATCH 128

__device__ __align__(16) float g_feat[NB * NC * HW];
__device__ float g_pp[NBC * 4 * 25];
__device__ float g_filt[NBC * 25];
__device__ int g_mix_done[NB];
__device__ int g_pool_done[NB];
__device__ int g_filt_done[NB];

__device__ __forceinline__ void launch_dependents() {
    asm volatile("griddepcontrol.launch_dependents;" ::: "memory");
}

// ---------------------------------------------------------------------------
// Kernel 0: reset the cross-kernel progress counters (graph replays need
// deterministic state every launch).
// ---------------------------------------------------------------------------
__global__ void reset_kernel() {
    int t = threadIdx.x;
    if (t < NB) {
        g_mix_done[t]  = 0;
        g_pool_done[t] = 0;
        g_filt_done[t] = 0;
    }
}

// ---------------------------------------------------------------------------
// Kernel 1: FUSED channel-mix + adaptive-pool-partials (R9 config verbatim),
// plus per-batch completion counters and an early PDL trigger so the filt
// and conv kernels can start backfilling this kernel's tail waves.
// grid = 3072, block = 256
// ---------------------------------------------------------------------------
__global__ __launch_bounds__(256) void mixpool_kernel(
    const float* __restrict__ x,
    const float* __restrict__ w,
    const float* __restrict__ bias)
{
    launch_dependents();   // fires once all blocks are resident -> tail overlap

    if (blockIdx.x < MIX_BLOCKS) {
        // ------------------------- mix path -------------------------
        __shared__ float ws[32 * 32];   // [i][o] transposed
        __shared__ float bs[32];

        int tid = threadIdx.x;
        for (int idx = tid; idx < 1024; idx += 256) {
            int i = idx >> 5, o = idx & 31;
            ws[i * 32 + o] = w[o * 32 + i];
        }
        if (tid < 32)
            bs[tid] = bias[tid];
        __syncthreads();

        int wid  = tid >> 5;
        int lane = tid & 31;
        int g = wid & 1;               // och group: g*16 .. g*16+15
        int s = wid >> 1;              // px segment (64 px each)

        int b  = blockIdx.x >> 8;      // batch
        int cx = blockIdx.x & 255;     // 256-px chunk within image
        size_t pixpair = (size_t)cx * 128 + s * 32 + lane;   // float2 idx
        const float2* xp = (const float2*)x
                         + (size_t)b * (NC * (HW / 2)) + pixpair;

        float ax[16], ay[16];
#pragma unroll
        for (int k = 0; k < 16; k++) {
            float bv = bs[g * 16 + k];
            ax[k] = bv;
            ay[k] = bv;
        }

#pragma unroll 8
        for (int i = 0; i < 32; i++) {
            float2 xv = xp[(size_t)i * (HW / 2)];
            const float4* wr = (const float4*)(ws + i * 32 + g * 16);
            float4 w0 = wr[0], w1 = wr[1], w2 = wr[2], w3 = wr[3];
            float wv[16] = {w0.x, w0.y, w0.z, w0.w, w1.x, w1.y, w1.z, w1.w,
                            w2.x, w2.y, w2.z, w2.w, w3.x, w3.y, w3.z, w3.w};
#pragma unroll
            for (int k = 0; k < 16; k++) {
                ax[k] = fmaf(wv[k], xv.x, ax[k]);
                ay[k] = fmaf(wv[k], xv.y, ay[k]);
            }
        }

        float2* fb = (float2*)g_feat + (size_t)b * (NC * (HW / 2)) + pixpair;
#pragma unroll
        for (int k = 0; k < 16; k++)
            fb[(size_t)(g * 16 + k) * (HW / 2)] = make_float2(ax[k], ay[k]);

        __threadfence();
        __syncthreads();
        if (tid == 0)
            atomicAdd(&g_mix_done[b], 1);

    } else {
        // ------------------------- pool path -------------------------
        // Row bins [0,52)[51,103)[102,154)[153,205)[204,256) (overlap).
        __shared__ float pool[25];
        int idx = blockIdx.x - MIX_BLOCKS;
        int bc = idx >> 2;             // (b*32 + channel)
        int q  = idx & 3;              // 64-row chunk
        int w_ = threadIdx.x;          // column
        if (w_ < 25) pool[w_] = 0.0f;
        __syncthreads();

        const float* img = x + (size_t)bc * HW + (size_t)q * 64 * 256;

        float cs[5] = {0.f, 0.f, 0.f, 0.f, 0.f};
#pragma unroll
        for (int r = 0; r < 64; r++) {
            int h = q * 64 + r;
            float v = img[r * 256 + w_];
            if (h < 52)              cs[0] += v;
            if (h >= 51 && h < 103)  cs[1] += v;
            if (h >= 102 && h < 154) cs[2] += v;
            if (h >= 153 && h < 205) cs[3] += v;
            if (h >= 204)            cs[4] += v;
        }

#pragma unroll
        for (int l = 0; l < 5; l++) {
            int s0 = (l * 256) / 5;
            int e0 = ((l + 1) * 256 + 4) / 5;
            if (w_ >= s0 && w_ < e0) {
#pragma unroll
                for (int k = 0; k < 5; k++)
                    if (cs[k] != 0.0f)
                        atomicAdd(&pool[k * 5 + l], cs[k]);
            }
        }
        __syncthreads();
        if (w_ < 25)
            g_pp[(bc * 4 + q) * 25 + w_] = pool[w_];

        __threadfence();
        __syncthreads();
        if (w_ == 0)
            atomicAdd(&g_pool_done[bc >> 5], 1);
    }
}

// ---------------------------------------------------------------------------
// Kernel 2: filt[b,o,kl] = bias[o] + sum_i w[o,i] * px[b,i,kl]
// PDL-overlapped; spins on pool completion for its batch.
// grid = 8, block = 800
// ---------------------------------------------------------------------------
__global__ void filt_kernel(const float* __restrict__ w,
                            const float* __restrict__ bias)
{
    launch_dependents();

    __shared__ float spx[800];
    int b = blockIdx.x;
    int t = threadIdx.x;

    if (t == 0) {
        volatile int* pd = (volatile int*)&g_pool_done[b];
        while (*pd < POOL_PER_BATCH) __nanosleep(128);
        __threadfence();
    }
    __syncthreads();

    int i  = t / 25;
    int kl = t - i * 25;

    float s = 0.0f;
#pragma unroll
    for (int q = 0; q < 4; q++)
        s += g_pp[((b * 32 + i) * 4 + q) * 25 + kl];
    spx[t] = s * (1.0f / 2704.0f);
    __syncthreads();

    float acc = bias[i];
#pragma unroll
    for (int ic = 0; ic < 32; ic++)
        acc += w[i * 32 + ic] * spx[ic * 25 + kl];
    g_filt[b * 800 + t] = acc;

    __threadfence();
    __syncthreads();
    if (t == 0)
        atomicExch(&g_filt_done[b], 1);
}

// ---------------------------------------------------------------------------
// Kernel 3: depthwise 5x5 'same' conv (R7 config: 38 us, occ 91%).
// PDL-overlapped; each block spins until its batch's feat + filter are
// ready, so conv backfills mixpool's tail waves batch-by-batch.
// grid = (32, 256), block = 256
// ---------------------------------------------------------------------------
__global__ __launch_bounds__(256) void conv_kernel(float* __restrict__ out)
{
    __shared__ float sh[36 * 68];

    int bc  = blockIdx.y;
    int b   = bc >> 5;

    if (threadIdx.x == 0) {
        volatile int* md = (volatile int*)&g_mix_done[b];
        volatile int* fd = (volatile int*)&g_filt_done[b];
        while (*md < MIX_PER_BATCH) __nanosleep(256);
        while (*fd == 0) __nanosleep(256);
        __threadfence();
    }
    __syncthreads();

    int tile = blockIdx.x;
    int tx0 = (tile & 3) * 64;
    int ty0 = (tile >> 2) * 32;

    const float* img = g_feat + (size_t)bc * HW;

    float f[25];
#pragma unroll
    for (int t = 0; t < 25; t++) f[t] = g_filt[bc * 25 + t];

    {
        int c  = threadIdx.x & 63;
        int r0 = threadIdx.x >> 6;
        int gx = tx0 + c - 2;
        bool cin = (unsigned)gx < 256u;
#pragma unroll
        for (int k = 0; k < 9; k++) {
            int r = r0 + k * 4;
            int gy = ty0 + r - 2;
            float v = 0.0f;
            if (cin && (unsigned)gy < 256u)
                v = img[gy * 256 + gx];
            sh[r * 68 + c] = v;
        }
        int c2 = 64 + (threadIdx.x & 3);
        int r2 = threadIdx.x >> 2;
        if (r2 < 36) {
            int gy = ty0 + r2 - 2;
            int gx2 = tx0 + c2 - 2;
            float v = 0.0f;
            if ((unsigned)gy < 256u && (unsigned)gx2 < 256u)
                v = img[gy * 256 + gx2];
            sh[r2 * 68 + c2] = v;
        }
    }
    __syncthreads();

    int x  = threadIdx.x & 63;
    int ys = (threadIdx.x >> 6) * 8;

    float acc[8];
#pragma unroll
    for (int j = 0; j < 8; j++) acc[j] = 0.0f;

#pragma unroll
    for (int r = 0; r < 12; r++) {
        const float* row = sh + (ys + r) * 68 + x;
        float v0 = row[0];
        float v1 = row[1];
        float v2 = row[2];
        float v3 = row[3];
        float v4 = row[4];
#pragma unroll
        for (int ky = 0; ky < 5; ky++) {
            int j = r - ky;
            if (j >= 0 && j < 8) {
                acc[j] += v0 * f[ky * 5 + 0];
                acc[j] += v1 * f[ky * 5 + 1];
                acc[j] += v2 * f[ky * 5 + 2];
                acc[j] += v3 * f[ky * 5 + 3];
                acc[j] += v4 * f[ky * 5 + 4];
            }
        }
    }

    float* op = out + (size_t)bc * HW + (size_t)(ty0 + ys) * 256 + tx0 + x;
#pragma unroll
    for (int j = 0; j < 8; j++)
        op[j * 256] = acc[j];
}

// ---------------------------------------------------------------------------
extern "C" void kernel_launch(void* const* d_in, const int* in_sizes, int n_in,
                              void* d_out, int out_size)
{
    const float* x    = (const float*)d_in[0];   // [8, 32, 256, 256]
    const float* w    = (const float*)d_in[1];   // [32, 32]
    const float* bias = (const float*)d_in[2];   // [32]
    float* out = (float*)d_out;                  // [8, 32, 256, 256]

    reset_kernel<<<1, 32>>>();
    mixpool_kernel<<<MIX_BLOCKS + POOL_BLOCKS, 256>>>(x, w, bias);

    cudaLaunchAttribute attr[1];
    attr[0].id = cudaLaunchAttributeProgrammaticStreamSerialization;
    attr[0].val.programmaticStreamSerializationAllowed = 1;

    {   // filt: PDL-overlapped into mixpool's tail
        cudaLaunchConfig_t cfg = {};
        cfg.gridDim = dim3(NB);
        cfg.blockDim = dim3(800);
        cfg.attrs = attr;
        cfg.numAttrs = 1;
        cudaLaunchKernelEx(&cfg, filt_kernel, w, bias);
    }
    {   // conv: PDL-overlapped, spin-guarded per batch
        cudaLaunchConfig_t cfg = {};
        cfg.gridDim = dim3(32, NBC);
        cfg.blockDim = dim3(256);
        cfg.attrs = attr;
        cfg.numAttrs = 1;
        cudaLaunchKernelEx(&cfg, conv_kernel, out);
    }
}